// round 15
// baseline (speedup 1.0000x reference)
#include <cuda_runtime.h>

// ---------------------------------------------------------------------------
// SparseCoupleDeConvTest: stride-2 sparse conv3d (CIN=32 -> COUT=64, K=3)
// followed by its exact adjoint, masked to the sparse coords, channel-major.
//
// Point-driven incidence enumeration: for a point at v, the (mid voxel o, tap t)
// pairs with 2o+t=v are EXACTLY the incidences of BOTH the forward conv
// (mid[o] += feat(v) . w1[t]) and the adjoint (out(v) += mid[o] . w2[t]).
// One binned list (by tap, 27 buckets) feeds two weight-stationary GEMM
// stages. Each PAIR is processed by a 2-warp team: warp-half h keeps a 32-reg
// scalar weight slice stationary, reads the activation via uniform-address
// broadcast LDGs, and folds with one coalesced REDG. Low registers -> high
// occupancy -> latency hidden.
// ---------------------------------------------------------------------------

typedef unsigned long long ull;

namespace {
constexpr int Dz = 41, Hy = 159, Wx = 159;
constexpr int OD = 20, OH = 79, OW = 79;
constexpr int CIN = 32, COUT = 64;
constexpr int NMID = 2 * OD * OH * OW;          // 249,640
constexpr int MAXB = 40960;                     // per-bucket capacity (exp ~18.8k)
constexpr int MAXPTS = 150016;
constexpr int BPT  = 24;                        // blocks per bucket in gemm kernels
constexpr int TEAMS = BPT * 4;                  // pair-teams striding a bucket
}

// Scratch (allocation-free: __device__ globals)
__device__ float g_mid[(size_t)NMID * COUT];    // dense mid activations (~64 MB)
__device__ float g_acc[(size_t)MAXPTS * CIN];   // per-point output accumulators
__device__ float g_w2t[27 * COUT * CIN];        // w2 transposed: [k][j][i]
__device__ int   g_cnt[27];                     // bucket counts
__device__ int2  g_bin[27 * (size_t)MAXB];      // (mid voxel, point)

// ---- launch #1: zero output + mid + acc + counters -------------------------
__global__ void zero_fill_kernel(float4* __restrict__ out, int n4, int nacc4) {
    int i = blockIdx.x * blockDim.x + threadIdx.x;
    int stride = gridDim.x * blockDim.x;
    float4 z = make_float4(0.f, 0.f, 0.f, 0.f);
    for (int j = i; j < n4; j += stride) out[j] = z;
    float4* midv = (float4*)g_mid;
    for (int j = i; j < NMID * (COUT / 4); j += stride) midv[j] = z;
    float4* accv = (float4*)g_acc;
    for (int j = i; j < nacc4; j += stride) accv[j] = z;
    if (i < 27) g_cnt[i] = 0;
}

// ---- launch #2: point-driven binning (block-aggregated atomics) -------------
// Candidate mid coords per dim: 2o + k = v, k in {0,1,2}, 0 <= o < O.
__device__ __forceinline__ int cands(int v, int O, int* os, int* ks) {
    if (v & 1) { os[0] = v >> 1; ks[0] = 1; return 1; }
    int n = 0, h = v >> 1;
    if (h < O) { os[n] = h;     ks[n] = 0; n++; }
    if (h > 0) { os[n] = h - 1; ks[n] = 2; n++; }
    return n;
}

__global__ __launch_bounds__(256) void bin_kernel(const int* __restrict__ coors,
                                                  int npts) {
    __shared__ int scnt[27], sbase[27];
    int tid = threadIdx.x;
    if (tid < 27) scnt[tid] = 0;
    __syncthreads();

    int n = blockIdx.x * 256 + tid;
    int4 c;
    int oz[2], kz[2], oy[2], ky[2], ox[2], kx[2];
    int na = 0, nb = 0, nc = 0;
    if (n < npts) {
        c = ((const int4*)coors)[n];
        na = cands(c.y, OD, oz, kz);
        nb = cands(c.z, OH, oy, ky);
        nc = cands(c.w, OW, ox, kx);
        for (int a = 0; a < na; a++)
            for (int bb = 0; bb < nb; bb++)
                for (int cc = 0; cc < nc; cc++)
                    atomicAdd(&scnt[(kz[a] * 3 + ky[bb]) * 3 + kx[cc]], 1);
    }
    __syncthreads();
    if (tid < 27) {
        sbase[tid] = atomicAdd(&g_cnt[tid], scnt[tid]);   // 27 globals per block
        scnt[tid] = 0;
    }
    __syncthreads();
    if (n < npts) {
        for (int a = 0; a < na; a++)
            for (int bb = 0; bb < nb; bb++)
                for (int cc = 0; cc < nc; cc++) {
                    int k  = (kz[a] * 3 + ky[bb]) * 3 + kx[cc];
                    int mo = ((c.x * OD + oz[a]) * OH + oy[bb]) * OW + ox[cc];
                    int pos = sbase[k] + atomicAdd(&scnt[k], 1);
                    if (pos < MAXB)
                        g_bin[(size_t)k * MAXB + pos] = make_int2(mo, n);
                }
    }
}

// ---- launch #3: transpose w2 (K,K,K,CIN,COUT) -> [k][j][i] ------------------
__global__ void build_w2t_kernel(const float* __restrict__ w2) {
    int id = blockIdx.x * blockDim.x + threadIdx.x;
    if (id >= 27 * COUT * CIN) return;
    int i = id & 31;
    int j = (id >> 5) & 63;
    int k = id >> 11;
    g_w2t[id] = __ldg(w2 + k * 2048 + i * 64 + j);
}

// ---- launch #4 (profiled): stage-1 GEMM, weight-stationary ------------------
// Bucket t = blockIdx.x % 27. 2-warp team per pair stream; warp-half h owns
// couts [32h,32h+32). W[i] = w1[t][i][32h+lane] (32 scalar regs, coalesced
// one-time load straight from w1). Per pair: uniform bin LDG + 8 uniform
// float4 feature broadcasts + 32 FFMA (4 chains) + 1 coalesced REDG.
__global__ __launch_bounds__(256, 3) void gemm1_kernel(
    const float* __restrict__ features, const float* __restrict__ w1) {
    int t     = blockIdx.x % 27;
    int chunk = blockIdx.x / 27;            // 0..BPT-1
    int w     = threadIdx.x >> 5;           // 0..7
    int team  = w >> 1;                     // 0..3
    int half  = w & 1;
    int lane  = threadIdx.x & 31;
    int nt = g_cnt[t];

    float W[32];
    {
        const float* wb = w1 + t * 2048 + half * 32 + lane;
#pragma unroll
        for (int i = 0; i < 32; i++) W[i] = __ldg(wb + i * 64);
    }

    const int2* bin = g_bin + (size_t)t * MAXB;
    for (int p = chunk * 4 + team; p < nt; p += TEAMS) {
        int2 pr = __ldg(bin + p);                         // uniform 8B
        const float4* f4 = (const float4*)(features + (size_t)pr.y * CIN);
        float a0 = 0.f, a1 = 0.f, a2 = 0.f, a3 = 0.f;
#pragma unroll
        for (int q = 0; q < 8; q++) {
            float4 f = __ldg(f4 + q);                     // uniform 16B broadcast
            a0 = fmaf(f.x, W[4 * q + 0], a0);
            a1 = fmaf(f.y, W[4 * q + 1], a1);
            a2 = fmaf(f.z, W[4 * q + 2], a2);
            a3 = fmaf(f.w, W[4 * q + 3], a3);
        }
        float r = (a0 + a1) + (a2 + a3);
        atomicAdd(g_mid + (size_t)pr.x * COUT + half * 32 + lane, r);  // REDG
    }
}

// ---- launch #5: stage-2 GEMM (adjoint), weight-stationary -------------------
// Lane = input channel i; warp-half h reduces over couts j in [32h,32h+32).
// W[j'] = w2t[k][32h+j'][lane] (coalesced). Per pair: uniform bin LDG +
// 8 uniform float4 mid-row broadcasts + 32 FFMA + 1 coalesced REDG into
// g_acc[pt][lane] (both halves fold into the same address).
__global__ __launch_bounds__(256, 3) void gemm2_kernel() {
    int k     = blockIdx.x % 27;
    int chunk = blockIdx.x / 27;
    int w     = threadIdx.x >> 5;
    int team  = w >> 1;
    int half  = w & 1;
    int lane  = threadIdx.x & 31;
    int nt = g_cnt[k];

    float W[32];
    {
        const float* wb = g_w2t + k * 2048 + (half * 32) * 32 + lane;
#pragma unroll
        for (int j = 0; j < 32; j++) W[j] = __ldg(wb + j * 32);
    }

    const int2* bin = g_bin + (size_t)k * MAXB;
    for (int p = chunk * 4 + team; p < nt; p += TEAMS) {
        int2 pr = __ldg(bin + p);                         // uniform 8B
        const float4* m4 = (const float4*)(g_mid + (size_t)pr.x * COUT + half * 32);
        float a0 = 0.f, a1 = 0.f, a2 = 0.f, a3 = 0.f;
#pragma unroll
        for (int q = 0; q < 8; q++) {
            float4 f = __ldg(m4 + q);                     // uniform 16B broadcast
            a0 = fmaf(f.x, W[4 * q + 0], a0);
            a1 = fmaf(f.y, W[4 * q + 1], a1);
            a2 = fmaf(f.z, W[4 * q + 2], a2);
            a3 = fmaf(f.w, W[4 * q + 3], a3);
        }
        float r = (a0 + a1) + (a2 + a3);
        atomicAdd(g_acc + (size_t)pr.y * CIN + lane, r);  // REDG, coalesced
    }
}

// ---- launch #6: scatter accumulators to channel-major output ----------------
__global__ void scatter_out_kernel(const int* __restrict__ coors, int npts,
                                   float* __restrict__ out) {
    int gw   = (blockIdx.x * 256 + threadIdx.x) >> 5;
    int lane = threadIdx.x & 31;
    if (gw >= npts) return;
    int4 c = ((const int4*)coors)[gw];
    float v = g_acc[(size_t)gw * CIN + lane];
    size_t oidx = (((size_t)(c.x * CIN + lane)) * Dz + c.y) * ((size_t)Hy * Wx)
                + (size_t)c.z * Wx + c.w;
    out[oidx] = v;
}

// ---------------------------------------------------------------------------

extern "C" void kernel_launch(void* const* d_in, const int* in_sizes, int n_in,
                              void* d_out, int out_size) {
    if (n_in < 4) return;
    const float* features = (const float*)d_in[0];
    const int*   coors    = (const int*)d_in[1];
    const float* w1       = (const float*)d_in[n_in - 2];
    const float* w2       = (const float*)d_in[n_in - 1];
    float* out = (float*)d_out;
    int npts = in_sizes[1] / 4;
    if (npts > MAXPTS) npts = MAXPTS;

    int n4    = out_size / 4;
    int nacc4 = (npts * 32 + 3) / 4;

    zero_fill_kernel<<<4096, 256>>>((float4*)out, n4, nacc4);           // #1
    bin_kernel<<<(npts + 255) / 256, 256>>>(coors, npts);               // #2
    build_w2t_kernel<<<(27 * COUT * CIN + 255) / 256, 256>>>(w2);       // #3
    gemm1_kernel<<<27 * BPT, 256>>>(features, w1);                      // #4 (profiled)
    gemm2_kernel<<<27 * BPT, 256>>>();                                  // #5
    scatter_out_kernel<<<(npts + 7) / 8, 256>>>(coors, npts, out);      // #6
}

// round 16
// speedup vs baseline: 1.6101x; 1.6101x over previous
#include <cuda_runtime.h>

// ---------------------------------------------------------------------------
// SparseCoupleDeConvTest: stride-2 sparse conv3d (CIN=32 -> COUT=64, K=3)
// followed by its exact adjoint, masked to the sparse coords, channel-major.
//
// One incidence list (pairs (mid voxel, point) with 2o+t=v), binned by tap,
// feeds two weight-stationary GEMM stages. The reduction dimension of each
// stage is split in half across two bucket passes (atomics fold partials), so
// the stationary weight slice fits in 32 registers -> 3 blocks/SM occupancy.
// Inner loop per pair: batched coalesced gathers (MLP=4) -> smem broadcast ->
// 16 packed fma.f32x2 -> one reduction atomic.
// ---------------------------------------------------------------------------

typedef unsigned long long ull;

namespace {
constexpr int Dz = 41, Hy = 159, Wx = 159;
constexpr int OD = 20, OH = 79, OW = 79;
constexpr int CIN = 32, COUT = 64;
constexpr int NMID = 2 * OD * OH * OW;          // 249,640
constexpr int NWQ  = 27 * 16 * 32;              // w2 repack granule count
constexpr int MAXB = 40960;                     // per-bucket capacity (exp ~18.8k)
constexpr int MAXPTS = 150016;
constexpr int BPT  = 16;                        // blocks per (tap,half) bucket
}

// Scratch (allocation-free: __device__ globals)
__device__ float      g_mid[(size_t)NMID * COUT];   // dense mid activations (~64 MB)
__device__ float      g_acc[(size_t)MAXPTS * CIN];  // per-point output accumulators
__device__ ulonglong2 g_w2q[NWQ];   // w2: [k][jp2][i] -> (w2[k,i,4jp2..4jp2+3])
__device__ int        g_cnt[27];                    // bucket counts
__device__ int2       g_bin[27 * (size_t)MAXB];     // (mid voxel, point)

// ---- packed fp32x2 helpers (sm_103a) --------------------------------------
__device__ __forceinline__ ull ffma2(ull a, ull b, ull c) {
    ull d;
    asm("fma.rn.f32x2 %0, %1, %2, %3;" : "=l"(d) : "l"(a), "l"(b), "l"(c));
    return d;
}
__device__ __forceinline__ ull fadd2(ull a, ull b) {
    ull d;
    asm("add.rn.f32x2 %0, %1, %2;" : "=l"(d) : "l"(a), "l"(b));
    return d;
}
__device__ __forceinline__ ull pack2(float x, float y) {
    ull r;
    asm("mov.b64 %0, {%1, %2};" : "=l"(r) : "f"(x), "f"(y));
    return r;
}
__device__ __forceinline__ float2 unpack2(ull a) {
    float2 r;
    asm("mov.b64 {%0, %1}, %2;" : "=f"(r.x), "=f"(r.y) : "l"(a));
    return r;
}
// vectorized fp32 reduction (sm_90+): one REDG for an adjacent float pair
__device__ __forceinline__ void red_add2(float* p, float x, float y) {
    asm volatile("{ .reg .u64 g; cvta.to.global.u64 g, %0;"
                 "  red.global.add.v2.f32 [g], {%1, %2}; }"
                 :: "l"(p), "f"(x), "f"(y) : "memory");
}

// ---- launch #1: zero output + mid + acc + counters -------------------------
__global__ void zero_fill_kernel(float4* __restrict__ out, int n4, int nacc4) {
    int i = blockIdx.x * blockDim.x + threadIdx.x;
    int stride = gridDim.x * blockDim.x;
    float4 z = make_float4(0.f, 0.f, 0.f, 0.f);
    for (int j = i; j < n4; j += stride) out[j] = z;
    float4* midv = (float4*)g_mid;
    for (int j = i; j < NMID * (COUT / 4); j += stride) midv[j] = z;
    float4* accv = (float4*)g_acc;
    for (int j = i; j < nacc4; j += stride) accv[j] = z;
    if (i < 27) g_cnt[i] = 0;
}

// ---- launch #2: point-driven binning (block-aggregated atomics) -------------
// Candidate mid coords per dim: 2o + k = v, k in {0,1,2}, 0 <= o < O.
__device__ __forceinline__ int cands(int v, int O, int* os, int* ks) {
    if (v & 1) { os[0] = v >> 1; ks[0] = 1; return 1; }
    int n = 0, h = v >> 1;
    if (h < O) { os[n] = h;     ks[n] = 0; n++; }
    if (h > 0) { os[n] = h - 1; ks[n] = 2; n++; }
    return n;
}

__global__ __launch_bounds__(256) void bin_kernel(const int* __restrict__ coors,
                                                  int npts) {
    __shared__ int scnt[27], sbase[27];
    int tid = threadIdx.x;
    if (tid < 27) scnt[tid] = 0;
    __syncthreads();

    int n = blockIdx.x * 256 + tid;
    int4 c;
    int oz[2], kz[2], oy[2], ky[2], ox[2], kx[2];
    int na = 0, nb = 0, nc = 0;
    if (n < npts) {
        c = ((const int4*)coors)[n];
        na = cands(c.y, OD, oz, kz);
        nb = cands(c.z, OH, oy, ky);
        nc = cands(c.w, OW, ox, kx);
        for (int a = 0; a < na; a++)
            for (int bb = 0; bb < nb; bb++)
                for (int cc = 0; cc < nc; cc++)
                    atomicAdd(&scnt[(kz[a] * 3 + ky[bb]) * 3 + kx[cc]], 1);
    }
    __syncthreads();
    if (tid < 27) {
        sbase[tid] = atomicAdd(&g_cnt[tid], scnt[tid]);   // 27 globals per block
        scnt[tid] = 0;
    }
    __syncthreads();
    if (n < npts) {
        for (int a = 0; a < na; a++)
            for (int bb = 0; bb < nb; bb++)
                for (int cc = 0; cc < nc; cc++) {
                    int k  = (kz[a] * 3 + ky[bb]) * 3 + kx[cc];
                    int mo = ((c.x * OD + oz[a]) * OH + oy[bb]) * OW + ox[cc];
                    int pos = sbase[k] + atomicAdd(&scnt[k], 1);
                    if (pos < MAXB)
                        g_bin[(size_t)k * MAXB + pos] = make_int2(mo, n);
                }
    }
}

// ---- launch #3: repack w2 into [k][jp2][i] 16B granules ---------------------
// w2 layout (K,K,K,CIN,COUT): flat = k*2048 + i*64 + j
__global__ void build_w2q_kernel(const float* __restrict__ w2) {
    int id = blockIdx.x * blockDim.x + threadIdx.x;
    if (id >= NWQ) return;
    int i = id & 31, jp2 = (id >> 5) & 15, k = id >> 9;
    float4 f = *(const float4*)(w2 + k * 2048 + i * 64 + 4 * jp2);
    ulonglong2 v;
    v.x = pack2(f.x, f.y);
    v.y = pack2(f.z, f.w);
    g_w2q[id] = v;
}

// ---- launch #4 (profiled): stage-1 GEMM, weight-stationary, cin-split -------
// Bucket (t, h) = (blockIdx.x % 27, (blockIdx.x/27) % 2); h = cin half.
// Lane l owns cout pair (2l, 2l+1); W[i'] = w1[t][16h+i'][2l:2l+2], 16 ull.
// Per pair: half feature row (64B) -> smem pack2 broadcast -> 8 LDS.128 +
// 16 FFMA2 -> partial REDG2 into g_mid (both halves fold atomically).
__global__ __launch_bounds__(256, 3) void gemm1_kernel(
    const float* __restrict__ features, const float* __restrict__ w1) {
    __shared__ __align__(16) ull sfeat[8][4][16];
    int t     = blockIdx.x % 27;
    int h     = (blockIdx.x / 27) & 1;
    int chunk = blockIdx.x / 54;            // 0..BPT-1
    int w     = threadIdx.x >> 5;           // 0..7
    int lane  = threadIdx.x & 31;
    int nt = g_cnt[t];

    ull W[16];
    {
        const ull* wu = (const ull*)w1;     // granule idx: t*1024 + i*32 + lane
        const ull* wb = wu + t * 1024 + (16 * h) * 32 + lane;
#pragma unroll
        for (int i = 0; i < 16; i++) W[i] = __ldg(wb + i * 32);
    }

    const int2* bin = g_bin + (size_t)t * MAXB;
    int fofs = 16 * h + (lane & 15);
    for (int base = (chunk * 8 + w) * 4; base < nt; base += BPT * 8 * 4) {
        int m = nt - base; if (m > 4) m = 4;
        int2 pr[4]; float f[4];
#pragma unroll
        for (int j = 0; j < 4; j++)
            if (j < m) {
                pr[j] = __ldg(bin + base + j);
                f[j]  = __ldg(features + (size_t)pr[j].y * CIN + fofs);   // 64B, MLP=4
            }
        __syncwarp();
#pragma unroll
        for (int j = 0; j < 4; j++)
            if (j < m && lane < 16) sfeat[w][j][lane] = pack2(f[j], f[j]);
        __syncwarp();
#pragma unroll
        for (int j = 0; j < 4; j++)
            if (j < m) {
                const ulonglong2* fq = (const ulonglong2*)sfeat[w][j];
                ull a0 = 0ull, a1 = 0ull;
#pragma unroll
                for (int g = 0; g < 8; g++) {
                    ulonglong2 fv = fq[g];
                    a0 = ffma2(fv.x, W[2 * g],     a0);
                    a1 = ffma2(fv.y, W[2 * g + 1], a1);
                }
                float2 r = unpack2(fadd2(a0, a1));
                red_add2(g_mid + (size_t)pr[j].x * COUT + 2 * lane, r.x, r.y);
            }
        __syncwarp();
    }
}

// ---- launch #5: stage-2 GEMM (adjoint), weight-stationary, j-split ----------
// Bucket (k, h); h = cout-j half. Lane = cin i. W2[m] = g_w2q granules for
// j in [32h+4m, 32h+4m+4), 8 ulonglong2. Per pair: half mid row (128B) ->
// smem -> 4 LDS.128 + 16 FFMA2 -> fold -> partial scalar REDG into g_acc.
__global__ __launch_bounds__(256, 3) void gemm2_kernel() {
    __shared__ __align__(16) ull srow[8][4][16];
    int k     = blockIdx.x % 27;
    int h     = (blockIdx.x / 27) & 1;
    int chunk = blockIdx.x / 54;
    int w     = threadIdx.x >> 5;
    int lane  = threadIdx.x & 31;
    int nt = g_cnt[k];

    ulonglong2 W2[8];
    {
        const ulonglong2* wb = g_w2q + (k * 16 + 8 * h) * 32 + lane;
#pragma unroll
        for (int m2 = 0; m2 < 8; m2++) W2[m2] = __ldg(wb + m2 * 32);
    }

    const int2* bin = g_bin + (size_t)k * MAXB;
    const ull* midu = (const ull*)g_mid;
    int mofs = 16 * h + (lane & 15);
    for (int base = (chunk * 8 + w) * 4; base < nt; base += BPT * 8 * 4) {
        int m = nt - base; if (m > 4) m = 4;
        int2 pr[4]; ull mv[4];
#pragma unroll
        for (int j = 0; j < 4; j++)
            if (j < m) {
                pr[j] = __ldg(bin + base + j);
                mv[j] = __ldg(midu + (size_t)pr[j].x * 32 + mofs);        // 128B, MLP=4
            }
        __syncwarp();
#pragma unroll
        for (int j = 0; j < 4; j++)
            if (j < m && lane < 16) srow[w][j][lane] = mv[j];
        __syncwarp();
#pragma unroll
        for (int j = 0; j < 4; j++)
            if (j < m) {
                const ulonglong2* mq = (const ulonglong2*)srow[w][j];
                ull a0 = 0ull, a1 = 0ull;
#pragma unroll
                for (int m2 = 0; m2 < 8; m2++) {
                    ulonglong2 fv = mq[m2];
                    a0 = ffma2(fv.x, W2[m2].x, a0);
                    a1 = ffma2(fv.y, W2[m2].y, a1);
                }
                float2 r = unpack2(fadd2(a0, a1));
                atomicAdd(g_acc + (size_t)pr[j].y * CIN + lane, r.x + r.y);
            }
        __syncwarp();
    }
}

// ---- launch #6: scatter accumulators to channel-major output ----------------
__global__ void scatter_out_kernel(const int* __restrict__ coors, int npts,
                                   float* __restrict__ out) {
    int gw   = (blockIdx.x * 256 + threadIdx.x) >> 5;
    int lane = threadIdx.x & 31;
    if (gw >= npts) return;
    int4 c = ((const int4*)coors)[gw];
    float v = g_acc[(size_t)gw * CIN + lane];
    size_t oidx = (((size_t)(c.x * CIN + lane)) * Dz + c.y) * ((size_t)Hy * Wx)
                + (size_t)c.z * Wx + c.w;
    out[oidx] = v;
}

// ---------------------------------------------------------------------------

extern "C" void kernel_launch(void* const* d_in, const int* in_sizes, int n_in,
                              void* d_out, int out_size) {
    if (n_in < 4) return;
    const float* features = (const float*)d_in[0];
    const int*   coors    = (const int*)d_in[1];
    const float* w1       = (const float*)d_in[n_in - 2];
    const float* w2       = (const float*)d_in[n_in - 1];
    float* out = (float*)d_out;
    int npts = in_sizes[1] / 4;
    if (npts > MAXPTS) npts = MAXPTS;

    int n4    = out_size / 4;
    int nacc4 = (npts * 32 + 3) / 4;

    zero_fill_kernel<<<4096, 256>>>((float4*)out, n4, nacc4);           // #1
    bin_kernel<<<(npts + 255) / 256, 256>>>(coors, npts);               // #2
    build_w2q_kernel<<<(NWQ + 255) / 256, 256>>>(w2);                   // #3
    gemm1_kernel<<<54 * BPT, 256>>>(features, w1);                      // #4 (profiled)
    gemm2_kernel<<<54 * BPT, 256>>>();                                  // #5
    scatter_out_kernel<<<(npts + 7) / 8, 256>>>(coors, npts, out);      // #6
}

// round 17
// speedup vs baseline: 1.6711x; 1.0379x over previous
#include <cuda_runtime.h>

// ---------------------------------------------------------------------------
// SparseCoupleDeConvTest: stride-2 sparse conv3d (CIN=32 -> COUT=64, K=3)
// followed by its exact adjoint, masked to the sparse coords, channel-major.
//
// One incidence list (pairs (mid voxel, point) with 2o+t=v), binned by tap,
// feeds two weight-stationary GEMM stages. The reduction dimension of each
// stage is split in half across two bucket passes (atomics fold partials), so
// the stationary weight slice fits in 32 registers -> 3 blocks/SM occupancy.
// gemm1 stages RAW floats in smem (4 LDS.128) and duplicates into packed
// fp32x2 operands in registers, minimizing L1 wavefronts (the measured binder).
// ---------------------------------------------------------------------------

typedef unsigned long long ull;

namespace {
constexpr int Dz = 41, Hy = 159, Wx = 159;
constexpr int OD = 20, OH = 79, OW = 79;
constexpr int CIN = 32, COUT = 64;
constexpr int NMID = 2 * OD * OH * OW;          // 249,640
constexpr int NWQ  = 27 * 16 * 32;              // w2 repack granule count
constexpr int MAXB = 40960;                     // per-bucket capacity (exp ~18.8k)
constexpr int MAXPTS = 150016;
constexpr int BPT  = 16;                        // blocks per (tap,half) bucket
}

// Scratch (allocation-free: __device__ globals)
__device__ float      g_mid[(size_t)NMID * COUT];   // dense mid activations (~64 MB)
__device__ float      g_acc[(size_t)MAXPTS * CIN];  // per-point output accumulators
__device__ ulonglong2 g_w2q[NWQ];   // w2: [k][jp2][i] -> (w2[k,i,4jp2..4jp2+3])
__device__ int        g_cnt[27];                    // bucket counts
__device__ int2       g_bin[27 * (size_t)MAXB];     // (mid voxel, point)

// ---- packed fp32x2 helpers (sm_103a) --------------------------------------
__device__ __forceinline__ ull ffma2(ull a, ull b, ull c) {
    ull d;
    asm("fma.rn.f32x2 %0, %1, %2, %3;" : "=l"(d) : "l"(a), "l"(b), "l"(c));
    return d;
}
__device__ __forceinline__ ull fadd2(ull a, ull b) {
    ull d;
    asm("add.rn.f32x2 %0, %1, %2;" : "=l"(d) : "l"(a), "l"(b));
    return d;
}
__device__ __forceinline__ ull pack2(float x, float y) {
    ull r;
    asm("mov.b64 %0, {%1, %2};" : "=l"(r) : "f"(x), "f"(y));
    return r;
}
__device__ __forceinline__ float2 unpack2(ull a) {
    float2 r;
    asm("mov.b64 {%0, %1}, %2;" : "=f"(r.x), "=f"(r.y) : "l"(a));
    return r;
}
// vectorized fp32 reduction (sm_90+): one REDG for an adjacent float pair
__device__ __forceinline__ void red_add2(float* p, float x, float y) {
    asm volatile("{ .reg .u64 g; cvta.to.global.u64 g, %0;"
                 "  red.global.add.v2.f32 [g], {%1, %2}; }"
                 :: "l"(p), "f"(x), "f"(y) : "memory");
}

// ---- launch #1: zero output + mid + acc + counters, and repack w2 ----------
// w2 layout (K,K,K,CIN,COUT): flat = k*2048 + i*64 + j
__global__ void zero_fill_w2q_kernel(float4* __restrict__ out, int n4, int nacc4,
                                     const float* __restrict__ w2) {
    int i = blockIdx.x * blockDim.x + threadIdx.x;
    int stride = gridDim.x * blockDim.x;
    float4 z = make_float4(0.f, 0.f, 0.f, 0.f);
    for (int j = i; j < n4; j += stride) out[j] = z;
    float4* midv = (float4*)g_mid;
    for (int j = i; j < NMID * (COUT / 4); j += stride) midv[j] = z;
    float4* accv = (float4*)g_acc;
    for (int j = i; j < nacc4; j += stride) accv[j] = z;
    if (i < 27) g_cnt[i] = 0;
    if (i < NWQ) {
        int ci = i & 31, jp2 = (i >> 5) & 15, k = i >> 9;
        float4 f = *(const float4*)(w2 + k * 2048 + ci * 64 + 4 * jp2);
        ulonglong2 v;
        v.x = pack2(f.x, f.y);
        v.y = pack2(f.z, f.w);
        g_w2q[i] = v;
    }
}

// ---- launch #2: point-driven binning (block-aggregated atomics) -------------
// Candidate mid coords per dim: 2o + k = v, k in {0,1,2}, 0 <= o < O.
__device__ __forceinline__ int cands(int v, int O, int* os, int* ks) {
    if (v & 1) { os[0] = v >> 1; ks[0] = 1; return 1; }
    int n = 0, h = v >> 1;
    if (h < O) { os[n] = h;     ks[n] = 0; n++; }
    if (h > 0) { os[n] = h - 1; ks[n] = 2; n++; }
    return n;
}

__global__ __launch_bounds__(256) void bin_kernel(const int* __restrict__ coors,
                                                  int npts) {
    __shared__ int scnt[27], sbase[27];
    int tid = threadIdx.x;
    if (tid < 27) scnt[tid] = 0;
    __syncthreads();

    int n = blockIdx.x * 256 + tid;
    int4 c;
    int oz[2], kz[2], oy[2], ky[2], ox[2], kx[2];
    int na = 0, nb = 0, nc = 0;
    if (n < npts) {
        c = ((const int4*)coors)[n];
        na = cands(c.y, OD, oz, kz);
        nb = cands(c.z, OH, oy, ky);
        nc = cands(c.w, OW, ox, kx);
        for (int a = 0; a < na; a++)
            for (int bb = 0; bb < nb; bb++)
                for (int cc = 0; cc < nc; cc++)
                    atomicAdd(&scnt[(kz[a] * 3 + ky[bb]) * 3 + kx[cc]], 1);
    }
    __syncthreads();
    if (tid < 27) {
        sbase[tid] = atomicAdd(&g_cnt[tid], scnt[tid]);   // 27 globals per block
        scnt[tid] = 0;
    }
    __syncthreads();
    if (n < npts) {
        for (int a = 0; a < na; a++)
            for (int bb = 0; bb < nb; bb++)
                for (int cc = 0; cc < nc; cc++) {
                    int k  = (kz[a] * 3 + ky[bb]) * 3 + kx[cc];
                    int mo = ((c.x * OD + oz[a]) * OH + oy[bb]) * OW + ox[cc];
                    int pos = sbase[k] + atomicAdd(&scnt[k], 1);
                    if (pos < MAXB)
                        g_bin[(size_t)k * MAXB + pos] = make_int2(mo, n);
                }
    }
}

// ---- launch #3: stage-1 GEMM, weight-stationary, cin-split ------------------
// Bucket (t, h) = (blockIdx.x % 27, (blockIdx.x/27) % 2); h = cin half.
// Lane l owns cout pair (2l, 2l+1); W[i'] = w1[t][16h+i'][2l:2l+2], 16 ull.
// Per pair: half feature row (64B) -> RAW-float smem stage (4 LDS.128
// broadcasts) -> in-register pack2 duplication -> 16 FFMA2 -> REDG2.
__global__ __launch_bounds__(256, 3) void gemm1_kernel(
    const float* __restrict__ features, const float* __restrict__ w1) {
    __shared__ float sfeat[8][4][16];
    int t     = blockIdx.x % 27;
    int h     = (blockIdx.x / 27) & 1;
    int chunk = blockIdx.x / 54;            // 0..BPT-1
    int w     = threadIdx.x >> 5;           // 0..7
    int lane  = threadIdx.x & 31;
    int nt = g_cnt[t];

    ull W[16];
    {
        const ull* wu = (const ull*)w1;     // granule idx: t*1024 + i*32 + lane
        const ull* wb = wu + t * 1024 + (16 * h) * 32 + lane;
#pragma unroll
        for (int i = 0; i < 16; i++) W[i] = __ldg(wb + i * 32);
    }

    const int2* bin = g_bin + (size_t)t * MAXB;
    int fofs = 16 * h + (lane & 15);
    for (int base = (chunk * 8 + w) * 4; base < nt; base += BPT * 8 * 4) {
        int m = nt - base; if (m > 4) m = 4;
        int2 pr[4]; float f[4];
#pragma unroll
        for (int j = 0; j < 4; j++)
            if (j < m) {
                pr[j] = __ldg(bin + base + j);
                f[j]  = __ldg(features + (size_t)pr[j].y * CIN + fofs);   // 64B, MLP=4
            }
        __syncwarp();   // also orders WAR on sfeat vs previous batch
#pragma unroll
        for (int j = 0; j < 4; j++)
            if (j < m && lane < 16) sfeat[w][j][lane] = f[j];
        __syncwarp();
#pragma unroll
        for (int j = 0; j < 4; j++)
            if (j < m) {
                const float4* fq4 = (const float4*)sfeat[w][j];
                ull a0 = 0ull, a1 = 0ull, a2 = 0ull, a3 = 0ull;
#pragma unroll
                for (int qi = 0; qi < 4; qi++) {
                    float4 fv = fq4[qi];                 // LDS.128 broadcast
                    a0 = ffma2(pack2(fv.x, fv.x), W[4 * qi + 0], a0);
                    a1 = ffma2(pack2(fv.y, fv.y), W[4 * qi + 1], a1);
                    a2 = ffma2(pack2(fv.z, fv.z), W[4 * qi + 2], a2);
                    a3 = ffma2(pack2(fv.w, fv.w), W[4 * qi + 3], a3);
                }
                float2 r = unpack2(fadd2(fadd2(a0, a1), fadd2(a2, a3)));
                red_add2(g_mid + (size_t)pr[j].x * COUT + 2 * lane, r.x, r.y);
            }
    }
}

// ---- launch #4 (profiled): stage-2 GEMM (adjoint), weight-stationary --------
// Bucket (k, h); h = cout-j half. Lane = cin i. W2[m] = g_w2q granules for
// j in [32h+4m, 32h+4m+4), 8 ulonglong2. Per pair: half mid row (128B) ->
// smem -> 8 LDS.128 + 16 FFMA2 -> fold -> partial scalar REDG into g_acc.
__global__ __launch_bounds__(256, 3) void gemm2_kernel() {
    __shared__ __align__(16) ull srow[8][4][16];
    int k     = blockIdx.x % 27;
    int h     = (blockIdx.x / 27) & 1;
    int chunk = blockIdx.x / 54;
    int w     = threadIdx.x >> 5;
    int lane  = threadIdx.x & 31;
    int nt = g_cnt[k];

    ulonglong2 W2[8];
    {
        const ulonglong2* wb = g_w2q + (k * 16 + 8 * h) * 32 + lane;
#pragma unroll
        for (int m2 = 0; m2 < 8; m2++) W2[m2] = __ldg(wb + m2 * 32);
    }

    const int2* bin = g_bin + (size_t)k * MAXB;
    const ull* midu = (const ull*)g_mid;
    int mofs = 16 * h + (lane & 15);
    for (int base = (chunk * 8 + w) * 4; base < nt; base += BPT * 8 * 4) {
        int m = nt - base; if (m > 4) m = 4;
        int2 pr[4]; ull mv[4];
#pragma unroll
        for (int j = 0; j < 4; j++)
            if (j < m) {
                pr[j] = __ldg(bin + base + j);
                mv[j] = __ldg(midu + (size_t)pr[j].x * 32 + mofs);        // 128B, MLP=4
            }
        __syncwarp();   // also orders WAR on srow vs previous batch
#pragma unroll
        for (int j = 0; j < 4; j++)
            if (j < m && lane < 16) srow[w][j][lane] = mv[j];
        __syncwarp();
#pragma unroll
        for (int j = 0; j < 4; j++)
            if (j < m) {
                const ulonglong2* mq = (const ulonglong2*)srow[w][j];
                ull a0 = 0ull, a1 = 0ull;
#pragma unroll
                for (int m2 = 0; m2 < 8; m2++) {
                    ulonglong2 fv = mq[m2];
                    a0 = ffma2(fv.x, W2[m2].x, a0);
                    a1 = ffma2(fv.y, W2[m2].y, a1);
                }
                float2 r = unpack2(fadd2(a0, a1));
                atomicAdd(g_acc + (size_t)pr[j].y * CIN + lane, r.x + r.y);
            }
    }
}

// ---- launch #5: scatter accumulators to channel-major output ----------------
__global__ void scatter_out_kernel(const int* __restrict__ coors, int npts,
                                   float* __restrict__ out) {
    int gw   = (blockIdx.x * 256 + threadIdx.x) >> 5;
    int lane = threadIdx.x & 31;
    if (gw >= npts) return;
    int4 c = ((const int4*)coors)[gw];
    float v = g_acc[(size_t)gw * CIN + lane];
    size_t oidx = (((size_t)(c.x * CIN + lane)) * Dz + c.y) * ((size_t)Hy * Wx)
                + (size_t)c.z * Wx + c.w;
    out[oidx] = v;
}

// ---------------------------------------------------------------------------

extern "C" void kernel_launch(void* const* d_in, const int* in_sizes, int n_in,
                              void* d_out, int out_size) {
    if (n_in < 4) return;
    const float* features = (const float*)d_in[0];
    const int*   coors    = (const int*)d_in[1];
    const float* w1       = (const float*)d_in[n_in - 2];
    const float* w2       = (const float*)d_in[n_in - 1];
    float* out = (float*)d_out;
    int npts = in_sizes[1] / 4;
    if (npts > MAXPTS) npts = MAXPTS;

    int n4    = out_size / 4;
    int nacc4 = (npts * 32 + 3) / 4;

    zero_fill_w2q_kernel<<<8192, 256>>>((float4*)out, n4, nacc4, w2);   // #1
    bin_kernel<<<(npts + 255) / 256, 256>>>(coors, npts);               // #2
    gemm1_kernel<<<54 * BPT, 256>>>(features, w1);                      // #3
    gemm2_kernel<<<54 * BPT, 256>>>();                                  // #4 (profiled)
    scatter_out_kernel<<<(npts + 7) / 8, 256>>>(coors, npts, out);      // #5
}